// round 6
// baseline (speedup 1.0000x reference)
#include <cuda_runtime.h>
#include <cuda_bf16.h>
#include <cstdint>

#define NMAX   131072      // B*INPUT_LEN
#define EMAX   4194304
#define ILEN   4096
#define PLEN   1024
#define WTOT   (NMAX / ILEN * PLEN)   // 32768 output elements
#define E1_GRID 4096                  // blocks in k_edge1 (contiguous chunks)

// Scratch (__device__ globals; allocation forbidden)
__device__ float  g_deg [NMAX];
__device__ float  g_dinv[NMAX];
__device__ float4 g_hs  [NMAX];   // raw h = x@W1, then h*dinv after k_node
__device__ float4 g_agg1[NMAX];   // layer1 unnormalized aggregator
__device__ float  g_t   [NMAX];   // layer2 pre-scaled messages t = h2*dinv
__device__ float  g_u   [WTOT];   // layer2 window accumulator (unnormalized)
__device__ int2   g_e2  [EMAX + 8]; // block-segmented compacted layer2 edges
__device__ int    g_cnt [E1_GRID];  // survivors per edge1 block

// ---------------------------------------------------------------------------
typedef unsigned long long ull;

__device__ __forceinline__ ull fma2(ull a, ull b, ull c) {
    ull d;
    asm("fma.rn.f32x2 %0, %1, %2, %3;" : "=l"(d) : "l"(a), "l"(b), "l"(c));
    return d;
}
__device__ __forceinline__ ull add2(ull a, ull b) {
    ull d;
    asm("add.rn.f32x2 %0, %1, %2;" : "=l"(d) : "l"(a), "l"(b));
    return d;
}
__device__ __forceinline__ ull pack2(float lo, float hi) {
    ull d;
    asm("mov.b64 %0, {%1, %2};" : "=l"(d) : "f"(lo), "f"(hi));
    return d;
}
__device__ __forceinline__ void unpack2(ull v, float& lo, float& hi) {
    asm("mov.b64 {%0, %1}, %2;" : "=f"(lo), "=f"(hi) : "l"(v));
}
__device__ __forceinline__ void red4(float4* p, float a, float b, float c) {
    size_t q = __cvta_generic_to_global(p);
    asm volatile("red.global.add.v4.f32 [%0], {%1, %2, %3, %4};"
                 :: "l"(q), "f"(a), "f"(b), "f"(c), "f"(0.0f) : "memory");
}

// ---------------------------------------------------------------------------
// K2 (fused): blocks [0, DEG_B): degree histogram (deg pre-zeroed by memset;
// +1 self loop applied in k_node); blocks [DEG_B, ...): raw h = x@W1.
#define DEG_B 384
__global__ __launch_bounds__(256)
void k_fused(const longlong2* __restrict__ Xll,
             const float* __restrict__ W1,
             const int* __restrict__ dst, int N, int E) {
    if (blockIdx.x < DEG_B) {
        int stride = DEG_B * blockDim.x;
        int i = blockIdx.x * blockDim.x + threadIdx.x;
        int E4 = E >> 2;
        const int4* dst4 = (const int4*)dst;
        for (int e = i; e < E4; e += stride) {
            int4 d = dst4[e];
            atomicAdd(&g_deg[d.x], 1.0f);
            atomicAdd(&g_deg[d.y], 1.0f);
            atomicAdd(&g_deg[d.z], 1.0f);
            atomicAdd(&g_deg[d.w], 1.0f);
        }
        for (int e = (E4 << 2) + i; e < E; e += stride)
            atomicAdd(&g_deg[dst[e]], 1.0f);
        return;
    }
    // linear path: 16 lanes per node, 4 nodes per warp iteration
    int lane = threadIdx.x & 31;
    int sub  = lane & 15;
    int half = lane >> 4;
    int warp = (((blockIdx.x - DEG_B) * blockDim.x) + threadIdx.x) >> 5;
    int nwarps = ((gridDim.x - DEG_B) * blockDim.x) >> 5;

    ull wp[4][3][2];
#pragma unroll
    for (int j = 0; j < 4; j++) {
        int c = sub + 16 * j;
#pragma unroll
        for (int k = 0; k < 3; k++) {
            wp[j][k][0] = pack2(W1[(4 * c + 0) * 3 + k], W1[(4 * c + 1) * 3 + k]);
            wp[j][k][1] = pack2(W1[(4 * c + 2) * 3 + k], W1[(4 * c + 3) * 3 + k]);
        }
    }

    int NG = N >> 2;
    for (int g = warp; g < NG; g += nwarps) {
        int nA = 4 * g + half;
        int nB = nA + 2;
        longlong2 va[4], vb[4];
        size_t baseA = (size_t)nA * 64 + sub;
        size_t baseB = (size_t)nB * 64 + sub;
#pragma unroll
        for (int j = 0; j < 4; j++) va[j] = Xll[baseA + 16 * j];
#pragma unroll
        for (int j = 0; j < 4; j++) vb[j] = Xll[baseB + 16 * j];

        ull aA0 = 0, aA1 = 0, aA2 = 0, aB0 = 0, aB1 = 0, aB2 = 0;
#pragma unroll
        for (int j = 0; j < 4; j++) {
            ull alo = (ull)va[j].x, ahi = (ull)va[j].y;
            ull blo = (ull)vb[j].x, bhi = (ull)vb[j].y;
            aA0 = fma2(alo, wp[j][0][0], aA0);  aA0 = fma2(ahi, wp[j][0][1], aA0);
            aA1 = fma2(alo, wp[j][1][0], aA1);  aA1 = fma2(ahi, wp[j][1][1], aA1);
            aA2 = fma2(alo, wp[j][2][0], aA2);  aA2 = fma2(ahi, wp[j][2][1], aA2);
            aB0 = fma2(blo, wp[j][0][0], aB0);  aB0 = fma2(bhi, wp[j][0][1], aB0);
            aB1 = fma2(blo, wp[j][1][0], aB1);  aB1 = fma2(bhi, wp[j][1][1], aB1);
            aB2 = fma2(blo, wp[j][2][0], aB2);  aB2 = fma2(bhi, wp[j][2][1], aB2);
        }
        float t0, t1;
        unpack2(aA0, t0, t1); float hA0 = t0 + t1;
        unpack2(aA1, t0, t1); float hA1 = t0 + t1;
        unpack2(aA2, t0, t1); float hA2 = t0 + t1;
        unpack2(aB0, t0, t1); float hB0 = t0 + t1;
        unpack2(aB1, t0, t1); float hB1 = t0 + t1;
        unpack2(aB2, t0, t1); float hB2 = t0 + t1;
        ull pA = pack2(hA0, hA1);
        ull pB = pack2(hB0, hB1);
#pragma unroll
        for (int off = 8; off; off >>= 1) {
            ull qA = __shfl_xor_sync(0xffffffffu, pA, off);
            ull qB = __shfl_xor_sync(0xffffffffu, pB, off);
            float rA = __shfl_xor_sync(0xffffffffu, hA2, off);
            float rB = __shfl_xor_sync(0xffffffffu, hB2, off);
            pA = add2(pA, qA);
            pB = add2(pB, qB);
            hA2 += rA;
            hB2 += rB;
        }
        if (sub == 0) {
            float x0, x1;
            unpack2(pA, x0, x1);
            g_hs[nA] = make_float4(x0, x1, hA2, 0.0f);
            unpack2(pB, x0, x1);
            g_hs[nB] = make_float4(x0, x1, hB2, 0.0f);
        }
    }
}

// K3: node pass — dinv = rsqrt(deg+1); hs = h*dinv; agg1 = hs (self loop)
__global__ void k_node(int N) {
    cudaGridDependencySynchronize();
    int n = blockIdx.x * blockDim.x + threadIdx.x;
    if (n >= N) return;
    float dv = rsqrtf(g_deg[n] + 1.0f);
    g_dinv[n] = dv;
    float4 h = g_hs[n];
    float4 hs = make_float4(h.x * dv, h.y * dv, h.z * dv, 0.0f);
    g_hs[n] = hs;
    g_agg1[n] = hs;
}

// K4: layer-1 scatter + contention-free layer-2 compaction.
// Exactly one int4 (4 edges) per thread in the common case; survivors kept in
// a tiny per-thread buffer, block writes them with ONE end-of-block scan.
__global__ __launch_bounds__(256)
void k_edge1(const int* __restrict__ ei, int E) {
    cudaGridDependencySynchronize();
    int E4 = E >> 2;
    int chunk4 = (E4 + E1_GRID - 1) / E1_GRID;        // 256 for E=4.19M
    int start4 = blockIdx.x * chunk4;
    int end4   = min(start4 + chunk4, E4);
    const int4* s4 = (const int4*)ei;
    const int4* d4 = (const int4*)(ei + E);

    int2 buf[4];
    int  cnt = 0;

    for (int e = start4 + threadIdx.x; e < end4; e += blockDim.x) {
        int4 s = s4[e];
        int4 d = d4[e];
        float4 h0 = g_hs[s.x];
        float4 h1 = g_hs[s.y];
        float4 h2 = g_hs[s.z];
        float4 h3 = g_hs[s.w];
        red4(&g_agg1[d.x], h0.x, h0.y, h0.z);
        red4(&g_agg1[d.y], h1.x, h1.y, h1.z);
        red4(&g_agg1[d.z], h2.x, h2.y, h2.z);
        red4(&g_agg1[d.w], h3.x, h3.y, h3.z);
        int r0 = d.x & (ILEN - 1);
        int r1 = d.y & (ILEN - 1);
        int r2 = d.z & (ILEN - 1);
        int r3 = d.w & (ILEN - 1);
        if (r0 < PLEN) buf[cnt++ & 3] = make_int2(s.x, (d.x >> 12) * PLEN + r0);
        if (r1 < PLEN) buf[cnt++ & 3] = make_int2(s.y, (d.y >> 12) * PLEN + r1);
        if (r2 < PLEN) buf[cnt++ & 3] = make_int2(s.z, (d.z >> 12) * PLEN + r2);
        if (r3 < PLEN) buf[cnt++ & 3] = make_int2(s.w, (d.w >> 12) * PLEN + r3);
    }
    // scalar tail (last block, E % 4 != 0): handled without compaction risk
    if (blockIdx.x == E1_GRID - 1) {
        for (int e = (E4 << 2) + threadIdx.x; e < E; e += blockDim.x) {
            int s = ei[e], d = ei[E + e];
            float4 h = g_hs[s];
            red4(&g_agg1[d], h.x, h.y, h.z);
            int r = d & (ILEN - 1);
            if (r < PLEN) buf[cnt++ & 3] = make_int2(s, (d >> 12) * PLEN + r);
        }
    }

    // ---- one block-level exclusive scan of per-thread counts ----
    __shared__ int warpTot[8];
    __shared__ int warpBase[8];
    int lane = threadIdx.x & 31;
    int wid  = threadIdx.x >> 5;
    int incl = cnt;
#pragma unroll
    for (int off = 1; off < 32; off <<= 1) {
        int v = __shfl_up_sync(0xffffffffu, incl, off);
        if (lane >= off) incl += v;
    }
    if (lane == 31) warpTot[wid] = incl;
    __syncthreads();
    if (threadIdx.x == 0) {
        int run = 0;
#pragma unroll
        for (int w = 0; w < 8; w++) { warpBase[w] = run; run += warpTot[w]; }
        g_cnt[blockIdx.x] = run;
    }
    __syncthreads();
    int2* slice = g_e2 + (size_t)start4 * 4;
    int ofs = warpBase[wid] + incl - cnt;
    for (int k = 0; k < cnt; k++) slice[ofs + k] = buf[k];
}

// K5: finalize layer1: a = agg1*dinv (+b1, relu) -> h2 -> t = h2*dinv.
//     Seed window accumulator g_u with self-loop term t[n].
__global__ void k_final1(const float* __restrict__ b1,
                         const float* __restrict__ W2, int N) {
    cudaGridDependencySynchronize();
    int n = blockIdx.x * blockDim.x + threadIdx.x;
    if (n >= N) return;
    float dv = g_dinv[n];
    float4 a = g_agg1[n];
    float o0 = fmaxf(a.x * dv + b1[0], 0.0f);
    float o1 = fmaxf(a.y * dv + b1[1], 0.0f);
    float o2 = fmaxf(a.z * dv + b1[2], 0.0f);
    float h2 = o0 * W2[0] + o1 * W2[1] + o2 * W2[2];
    float t = h2 * dv;
    g_t[n] = t;
    int r = n & (ILEN - 1);
    if (r < PLEN)
        g_u[(n >> 12) * PLEN + r] = t;
}

// K6: layer-2 scatter over block-segmented compacted edges: u[oidx] += t[src]
__global__ __launch_bounds__(256)
void k_edge2(int E) {
    cudaGridDependencySynchronize();
    int E4 = E >> 2;
    int chunk4 = (E4 + E1_GRID - 1) / E1_GRID;
    int cnt = g_cnt[blockIdx.x];
    const int2* slice = g_e2 + (size_t)blockIdx.x * chunk4 * 4;
    for (int i = threadIdx.x; i < cnt; i += blockDim.x) {
        int2 p = slice[i];
        atomicAdd(&g_u[p.y], g_t[p.x]);
    }
}

// K7: final output: out = u * dinv[node] + b2
__global__ void k_out(const float* __restrict__ b2, float* __restrict__ out) {
    cudaGridDependencySynchronize();
    int i = blockIdx.x * blockDim.x + threadIdx.x;
    if (i >= WTOT) return;
    int n = (i >> 10) * ILEN + (i & (PLEN - 1));
    out[i] = g_u[i] * g_dinv[n] + b2[0];
}

// ---------------------------------------------------------------------------
static void launch_pdl(const void* fn, dim3 grid, dim3 block, void** args) {
    cudaLaunchConfig_t cfg = {};
    cfg.gridDim  = grid;
    cfg.blockDim = block;
    cfg.stream   = 0;
    cudaLaunchAttribute attr[1];
    attr[0].id = cudaLaunchAttributeProgrammaticStreamSerialization;
    attr[0].val.programmaticStreamSerializationAllowed = 1;
    cfg.attrs = attr;
    cfg.numAttrs = 1;
    cudaLaunchKernelExC(&cfg, fn, args);
}

extern "C" void kernel_launch(void* const* d_in, const int* in_sizes, int n_in,
                              void* d_out, int out_size) {
    const float* X   = (const float*)d_in[0];   // [N,256]
    const float* W1  = (const float*)d_in[1];   // [256,3]
    const float* b1  = (const float*)d_in[2];   // [3]
    const float* W2  = (const float*)d_in[3];   // [3,1]
    const float* b2  = (const float*)d_in[4];   // [1]
    const int*   ei  = (const int*)d_in[5];     // [2,E]
    float*       out = (float*)d_out;

    int N = in_sizes[0] / 256;
    int E = in_sizes[5] / 2;

    const int T = 256;
    int nb_node = (N + T - 1) / T;

    // zero g_deg (replaces an init kernel; graph-capturable)
    void* deg_ptr = nullptr;
    cudaGetSymbolAddress(&deg_ptr, g_deg);
    cudaMemsetAsync(deg_ptr, 0, (size_t)N * sizeof(float));

    k_fused<<<DEG_B + 768, T>>>((const longlong2*)X, W1, ei + E, N, E);

    {   // k_node
        const longlong2* dummy = nullptr;
        (void)dummy;
        void* args[] = { &N };
        launch_pdl((const void*)k_node, dim3(nb_node), dim3(T), args);
    }
    {   // k_edge1
        void* args[] = { (void*)&ei, &E };
        launch_pdl((const void*)k_edge1, dim3(E1_GRID), dim3(T), args);
    }
    {   // k_final1
        void* args[] = { (void*)&b1, (void*)&W2, &N };
        launch_pdl((const void*)k_final1, dim3(nb_node), dim3(T), args);
    }
    {   // k_edge2
        void* args[] = { &E };
        launch_pdl((const void*)k_edge2, dim3(E1_GRID), dim3(T), args);
    }
    {   // k_out
        void* args[] = { (void*)&b2, (void*)&out };
        launch_pdl((const void*)k_out, dim3((WTOT + T - 1) / T), dim3(T), args);
    }
}

// round 7
// speedup vs baseline: 1.1528x; 1.1528x over previous
#include <cuda_runtime.h>
#include <cuda_bf16.h>
#include <cstdint>

#define NMAX   131072      // B*INPUT_LEN
#define ILEN   4096
#define PLEN   1024
#define WTOT   (NMAX / ILEN * PLEN)   // 32768 output elements

// Scratch (__device__ globals; allocation forbidden)
__device__ float  g_deg [NMAX];
__device__ float  g_dinv[NMAX];
__device__ float4 g_hs  [NMAX];   // raw h = x@W1, then h*dinv after k_node
__device__ float4 g_agg1[NMAX];   // layer1 unnormalized aggregator
__device__ float  g_t   [NMAX];   // layer2 pre-scaled messages t = h2*dinv
__device__ float  g_u   [WTOT];   // layer2 window accumulator (unnormalized)

// ---------------------------------------------------------------------------
typedef unsigned long long ull;

__device__ __forceinline__ ull fma2(ull a, ull b, ull c) {
    ull d;
    asm("fma.rn.f32x2 %0, %1, %2, %3;" : "=l"(d) : "l"(a), "l"(b), "l"(c));
    return d;
}
__device__ __forceinline__ ull add2(ull a, ull b) {
    ull d;
    asm("add.rn.f32x2 %0, %1, %2;" : "=l"(d) : "l"(a), "l"(b));
    return d;
}
__device__ __forceinline__ ull pack2(float lo, float hi) {
    ull d;
    asm("mov.b64 %0, {%1, %2};" : "=l"(d) : "f"(lo), "f"(hi));
    return d;
}
__device__ __forceinline__ void unpack2(ull v, float& lo, float& hi) {
    asm("mov.b64 {%0, %1}, %2;" : "=f"(lo), "=f"(hi) : "l"(v));
}
__device__ __forceinline__ void red4(float4* p, float a, float b, float c) {
    size_t q = __cvta_generic_to_global(p);
    asm volatile("red.global.add.v4.f32 [%0], {%1, %2, %3, %4};"
                 :: "l"(q), "f"(a), "f"(b), "f"(c), "f"(0.0f) : "memory");
}

// ---------------------------------------------------------------------------
// K2 (fused): blocks [0, DEG_B): degree histogram (deg pre-zeroed by memset;
// +1 self loop applied in k_node); blocks [DEG_B, ...): raw h = x@W1.
#define DEG_B 384
__global__ __launch_bounds__(256)
void k_fused(const longlong2* __restrict__ Xll,
             const float* __restrict__ W1,
             const int* __restrict__ dst, int N, int E) {
    if (blockIdx.x < DEG_B) {
        int stride = DEG_B * blockDim.x;
        int i = blockIdx.x * blockDim.x + threadIdx.x;
        int E4 = E >> 2;
        const int4* dst4 = (const int4*)dst;
        for (int e = i; e < E4; e += stride) {
            int4 d = dst4[e];
            atomicAdd(&g_deg[d.x], 1.0f);
            atomicAdd(&g_deg[d.y], 1.0f);
            atomicAdd(&g_deg[d.z], 1.0f);
            atomicAdd(&g_deg[d.w], 1.0f);
        }
        for (int e = (E4 << 2) + i; e < E; e += stride)
            atomicAdd(&g_deg[dst[e]], 1.0f);
        return;
    }
    // linear path: 16 lanes per node, 4 nodes per warp iteration
    int lane = threadIdx.x & 31;
    int sub  = lane & 15;
    int half = lane >> 4;
    int warp = (((blockIdx.x - DEG_B) * blockDim.x) + threadIdx.x) >> 5;
    int nwarps = ((gridDim.x - DEG_B) * blockDim.x) >> 5;

    ull wp[4][3][2];
#pragma unroll
    for (int j = 0; j < 4; j++) {
        int c = sub + 16 * j;
#pragma unroll
        for (int k = 0; k < 3; k++) {
            wp[j][k][0] = pack2(W1[(4 * c + 0) * 3 + k], W1[(4 * c + 1) * 3 + k]);
            wp[j][k][1] = pack2(W1[(4 * c + 2) * 3 + k], W1[(4 * c + 3) * 3 + k]);
        }
    }

    int NG = N >> 2;
    for (int g = warp; g < NG; g += nwarps) {
        int nA = 4 * g + half;
        int nB = nA + 2;
        longlong2 va[4], vb[4];
        size_t baseA = (size_t)nA * 64 + sub;
        size_t baseB = (size_t)nB * 64 + sub;
#pragma unroll
        for (int j = 0; j < 4; j++) va[j] = Xll[baseA + 16 * j];
#pragma unroll
        for (int j = 0; j < 4; j++) vb[j] = Xll[baseB + 16 * j];

        ull aA0 = 0, aA1 = 0, aA2 = 0, aB0 = 0, aB1 = 0, aB2 = 0;
#pragma unroll
        for (int j = 0; j < 4; j++) {
            ull alo = (ull)va[j].x, ahi = (ull)va[j].y;
            ull blo = (ull)vb[j].x, bhi = (ull)vb[j].y;
            aA0 = fma2(alo, wp[j][0][0], aA0);  aA0 = fma2(ahi, wp[j][0][1], aA0);
            aA1 = fma2(alo, wp[j][1][0], aA1);  aA1 = fma2(ahi, wp[j][1][1], aA1);
            aA2 = fma2(alo, wp[j][2][0], aA2);  aA2 = fma2(ahi, wp[j][2][1], aA2);
            aB0 = fma2(blo, wp[j][0][0], aB0);  aB0 = fma2(bhi, wp[j][0][1], aB0);
            aB1 = fma2(blo, wp[j][1][0], aB1);  aB1 = fma2(bhi, wp[j][1][1], aB1);
            aB2 = fma2(blo, wp[j][2][0], aB2);  aB2 = fma2(bhi, wp[j][2][1], aB2);
        }
        float t0, t1;
        unpack2(aA0, t0, t1); float hA0 = t0 + t1;
        unpack2(aA1, t0, t1); float hA1 = t0 + t1;
        unpack2(aA2, t0, t1); float hA2 = t0 + t1;
        unpack2(aB0, t0, t1); float hB0 = t0 + t1;
        unpack2(aB1, t0, t1); float hB1 = t0 + t1;
        unpack2(aB2, t0, t1); float hB2 = t0 + t1;
        ull pA = pack2(hA0, hA1);
        ull pB = pack2(hB0, hB1);
#pragma unroll
        for (int off = 8; off; off >>= 1) {
            ull qA = __shfl_xor_sync(0xffffffffu, pA, off);
            ull qB = __shfl_xor_sync(0xffffffffu, pB, off);
            float rA = __shfl_xor_sync(0xffffffffu, hA2, off);
            float rB = __shfl_xor_sync(0xffffffffu, hB2, off);
            pA = add2(pA, qA);
            pB = add2(pB, qB);
            hA2 += rA;
            hB2 += rB;
        }
        if (sub == 0) {
            float x0, x1;
            unpack2(pA, x0, x1);
            g_hs[nA] = make_float4(x0, x1, hA2, 0.0f);
            unpack2(pB, x0, x1);
            g_hs[nB] = make_float4(x0, x1, hB2, 0.0f);
        }
    }
}

// K3: node pass — dinv = rsqrt(deg+1); hs = h*dinv; agg1 = hs (self loop)
__global__ void k_node(int N) {
    cudaGridDependencySynchronize();
    int n = blockIdx.x * blockDim.x + threadIdx.x;
    if (n >= N) return;
    float dv = rsqrtf(g_deg[n] + 1.0f);
    g_dinv[n] = dv;
    float4 h = g_hs[n];
    float4 hs = make_float4(h.x * dv, h.y * dv, h.z * dv, 0.0f);
    g_hs[n] = hs;
    g_agg1[n] = hs;
}

// K4: layer-1 scatter: agg1[d] += hs[s]   (R3 version, 4 edges/thread)
__global__ __launch_bounds__(256)
void k_edge1(const int* __restrict__ ei, int E) {
    cudaGridDependencySynchronize();
    int stride = gridDim.x * blockDim.x;
    int i = blockIdx.x * blockDim.x + threadIdx.x;
    int E4 = E >> 2;
    const int4* s4 = (const int4*)ei;
    const int4* d4 = (const int4*)(ei + E);
    for (int e = i; e < E4; e += stride) {
        int4 s = s4[e];
        int4 d = d4[e];
        float4 h0 = g_hs[s.x];
        float4 h1 = g_hs[s.y];
        float4 h2 = g_hs[s.z];
        float4 h3 = g_hs[s.w];
        red4(&g_agg1[d.x], h0.x, h0.y, h0.z);
        red4(&g_agg1[d.y], h1.x, h1.y, h1.z);
        red4(&g_agg1[d.z], h2.x, h2.y, h2.z);
        red4(&g_agg1[d.w], h3.x, h3.y, h3.z);
    }
    for (int e = (E4 << 2) + i; e < E; e += stride) {
        int s = ei[e], d = ei[E + e];
        float4 h = g_hs[s];
        red4(&g_agg1[d], h.x, h.y, h.z);
    }
}

// K5: finalize layer1: a = agg1*dinv (+b1, relu) -> h2 -> t = h2*dinv.
//     Seed window accumulator g_u with self-loop term t[n].
__global__ void k_final1(const float* __restrict__ b1,
                         const float* __restrict__ W2, int N) {
    cudaGridDependencySynchronize();
    int n = blockIdx.x * blockDim.x + threadIdx.x;
    if (n >= N) return;
    float dv = g_dinv[n];
    float4 a = g_agg1[n];
    float o0 = fmaxf(a.x * dv + b1[0], 0.0f);
    float o1 = fmaxf(a.y * dv + b1[1], 0.0f);
    float o2 = fmaxf(a.z * dv + b1[2], 0.0f);
    float h2 = o0 * W2[0] + o1 * W2[1] + o2 * W2[2];
    float t = h2 * dv;
    g_t[n] = t;
    int r = n & (ILEN - 1);
    if (r < PLEN)
        g_u[(n >> 12) * PLEN + r] = t;
}

// K6: layer-2 scatter, filtered, unnormalized: u[d] += t[s]  (R3 version)
__global__ __launch_bounds__(256)
void k_edge2(const int* __restrict__ ei, int E) {
    cudaGridDependencySynchronize();
    int stride = gridDim.x * blockDim.x;
    int i = blockIdx.x * blockDim.x + threadIdx.x;
    int E4 = E >> 2;
    const int4* s4 = (const int4*)ei;
    const int4* d4 = (const int4*)(ei + E);
    for (int e = i; e < E4; e += stride) {
        int4 d = d4[e];
        int4 s = s4[e];
        int r0 = d.x & (ILEN - 1);
        int r1 = d.y & (ILEN - 1);
        int r2 = d.z & (ILEN - 1);
        int r3 = d.w & (ILEN - 1);
        if (r0 < PLEN) atomicAdd(&g_u[(d.x >> 12) * PLEN + r0], g_t[s.x]);
        if (r1 < PLEN) atomicAdd(&g_u[(d.y >> 12) * PLEN + r1], g_t[s.y]);
        if (r2 < PLEN) atomicAdd(&g_u[(d.z >> 12) * PLEN + r2], g_t[s.z]);
        if (r3 < PLEN) atomicAdd(&g_u[(d.w >> 12) * PLEN + r3], g_t[s.w]);
    }
    for (int e = (E4 << 2) + i; e < E; e += stride) {
        int d = ei[E + e];
        int r = d & (ILEN - 1);
        if (r < PLEN)
            atomicAdd(&g_u[(d >> 12) * PLEN + r], g_t[ei[e]]);
    }
}

// K7: final output: out = u * dinv[node] + b2
__global__ void k_out(const float* __restrict__ b2, float* __restrict__ out) {
    cudaGridDependencySynchronize();
    int i = blockIdx.x * blockDim.x + threadIdx.x;
    if (i >= WTOT) return;
    int n = (i >> 10) * ILEN + (i & (PLEN - 1));
    out[i] = g_u[i] * g_dinv[n] + b2[0];
}

// ---------------------------------------------------------------------------
static void launch_pdl(const void* fn, dim3 grid, dim3 block, void** args) {
    cudaLaunchConfig_t cfg = {};
    cfg.gridDim  = grid;
    cfg.blockDim = block;
    cfg.stream   = 0;
    cudaLaunchAttribute attr[1];
    attr[0].id = cudaLaunchAttributeProgrammaticStreamSerialization;
    attr[0].val.programmaticStreamSerializationAllowed = 1;
    cfg.attrs = attr;
    cfg.numAttrs = 1;
    cudaLaunchKernelExC(&cfg, fn, args);
}

extern "C" void kernel_launch(void* const* d_in, const int* in_sizes, int n_in,
                              void* d_out, int out_size) {
    const float* X   = (const float*)d_in[0];   // [N,256]
    const float* W1  = (const float*)d_in[1];   // [256,3]
    const float* b1  = (const float*)d_in[2];   // [3]
    const float* W2  = (const float*)d_in[3];   // [3,1]
    const float* b2  = (const float*)d_in[4];   // [1]
    const int*   ei  = (const int*)d_in[5];     // [2,E]
    float*       out = (float*)d_out;

    int N = in_sizes[0] / 256;
    int E = in_sizes[5] / 2;

    const int T = 256;
    int nb_node = (N + T - 1) / T;

    // zero g_deg (replaces an init kernel; graph-capturable)
    void* deg_ptr = nullptr;
    cudaGetSymbolAddress(&deg_ptr, g_deg);
    cudaMemsetAsync(deg_ptr, 0, (size_t)N * sizeof(float));

    const int* dstp = ei + E;
    {   // k_fused (first kernel after memset — plain launch)
        k_fused<<<DEG_B + 768, T>>>((const longlong2*)X, W1, dstp, N, E);
    }
    {   // k_node
        void* args[] = { &N };
        launch_pdl((const void*)k_node, dim3(nb_node), dim3(T), args);
    }
    {   // k_edge1
        void* args[] = { (void*)&ei, &E };
        launch_pdl((const void*)k_edge1, dim3(4096), dim3(T), args);
    }
    {   // k_final1
        void* args[] = { (void*)&b1, (void*)&W2, &N };
        launch_pdl((const void*)k_final1, dim3(nb_node), dim3(T), args);
    }
    {   // k_edge2
        void* args[] = { (void*)&ei, &E };
        launch_pdl((const void*)k_edge2, dim3(4096), dim3(T), args);
    }
    {   // k_out
        void* args[] = { (void*)&b2, (void*)&out };
        launch_pdl((const void*)k_out, dim3((WTOT + T - 1) / T), dim3(T), args);
    }
}

// round 8
// speedup vs baseline: 1.1532x; 1.0003x over previous
#include <cuda_runtime.h>
#include <cuda_bf16.h>
#include <cstdint>

#define NMAX   131072      // B*INPUT_LEN
#define ILEN   4096
#define PLEN   1024
#define WTOT   (NMAX / ILEN * PLEN)   // 32768 output elements

// Scratch (__device__ globals; allocation forbidden).
// INVARIANT: g_deg is all-zero at kernel_launch entry. It is zero at module
// load (.bss), and k_out re-zeroes it at the end of every execution, so every
// graph replay (and any sequential re-execution) sees the same state.
__device__ float  g_deg [NMAX];
__device__ float  g_dinv[NMAX];
__device__ float4 g_hs  [NMAX];   // raw h = x@W1, then h*dinv after k_node
__device__ float4 g_agg1[NMAX];   // layer1 unnormalized aggregator
__device__ float  g_t   [NMAX];   // layer2 pre-scaled messages t = h2*dinv
__device__ float  g_u   [WTOT];   // layer2 window accumulator (unnormalized)

// ---------------------------------------------------------------------------
typedef unsigned long long ull;

__device__ __forceinline__ ull fma2(ull a, ull b, ull c) {
    ull d;
    asm("fma.rn.f32x2 %0, %1, %2, %3;" : "=l"(d) : "l"(a), "l"(b), "l"(c));
    return d;
}
__device__ __forceinline__ ull add2(ull a, ull b) {
    ull d;
    asm("add.rn.f32x2 %0, %1, %2;" : "=l"(d) : "l"(a), "l"(b));
    return d;
}
__device__ __forceinline__ ull pack2(float lo, float hi) {
    ull d;
    asm("mov.b64 %0, {%1, %2};" : "=l"(d) : "f"(lo), "f"(hi));
    return d;
}
__device__ __forceinline__ void unpack2(ull v, float& lo, float& hi) {
    asm("mov.b64 {%0, %1}, %2;" : "=f"(lo), "=f"(hi) : "l"(v));
}
__device__ __forceinline__ void red4(float4* p, float a, float b, float c) {
    size_t q = __cvta_generic_to_global(p);
    asm volatile("red.global.add.v4.f32 [%0], {%1, %2, %3, %4};"
                 :: "l"(q), "f"(a), "f"(b), "f"(c), "f"(0.0f) : "memory");
}

// ---------------------------------------------------------------------------
// K2 (fused): blocks [0, DEG_B): degree histogram (deg zero at entry; +1 self
// loop applied in k_node); blocks [DEG_B, ...): raw h = x@W1.
#define DEG_B 384
__global__ __launch_bounds__(256)
void k_fused(const longlong2* __restrict__ Xll,
             const float* __restrict__ W1,
             const int* __restrict__ dst, int N, int E) {
    if (blockIdx.x < DEG_B) {
        int stride = DEG_B * blockDim.x;
        int i = blockIdx.x * blockDim.x + threadIdx.x;
        int E4 = E >> 2;
        const int4* dst4 = (const int4*)dst;
        for (int e = i; e < E4; e += stride) {
            int4 d = dst4[e];
            atomicAdd(&g_deg[d.x], 1.0f);
            atomicAdd(&g_deg[d.y], 1.0f);
            atomicAdd(&g_deg[d.z], 1.0f);
            atomicAdd(&g_deg[d.w], 1.0f);
        }
        for (int e = (E4 << 2) + i; e < E; e += stride)
            atomicAdd(&g_deg[dst[e]], 1.0f);
        return;
    }
    // linear path: 16 lanes per node, 4 nodes per warp iteration
    int lane = threadIdx.x & 31;
    int sub  = lane & 15;
    int half = lane >> 4;
    int warp = (((blockIdx.x - DEG_B) * blockDim.x) + threadIdx.x) >> 5;
    int nwarps = ((gridDim.x - DEG_B) * blockDim.x) >> 5;

    ull wp[4][3][2];
#pragma unroll
    for (int j = 0; j < 4; j++) {
        int c = sub + 16 * j;
#pragma unroll
        for (int k = 0; k < 3; k++) {
            wp[j][k][0] = pack2(W1[(4 * c + 0) * 3 + k], W1[(4 * c + 1) * 3 + k]);
            wp[j][k][1] = pack2(W1[(4 * c + 2) * 3 + k], W1[(4 * c + 3) * 3 + k]);
        }
    }

    int NG = N >> 2;
    for (int g = warp; g < NG; g += nwarps) {
        int nA = 4 * g + half;
        int nB = nA + 2;
        longlong2 va[4], vb[4];
        size_t baseA = (size_t)nA * 64 + sub;
        size_t baseB = (size_t)nB * 64 + sub;
#pragma unroll
        for (int j = 0; j < 4; j++) va[j] = Xll[baseA + 16 * j];
#pragma unroll
        for (int j = 0; j < 4; j++) vb[j] = Xll[baseB + 16 * j];

        ull aA0 = 0, aA1 = 0, aA2 = 0, aB0 = 0, aB1 = 0, aB2 = 0;
#pragma unroll
        for (int j = 0; j < 4; j++) {
            ull alo = (ull)va[j].x, ahi = (ull)va[j].y;
            ull blo = (ull)vb[j].x, bhi = (ull)vb[j].y;
            aA0 = fma2(alo, wp[j][0][0], aA0);  aA0 = fma2(ahi, wp[j][0][1], aA0);
            aA1 = fma2(alo, wp[j][1][0], aA1);  aA1 = fma2(ahi, wp[j][1][1], aA1);
            aA2 = fma2(alo, wp[j][2][0], aA2);  aA2 = fma2(ahi, wp[j][2][1], aA2);
            aB0 = fma2(blo, wp[j][0][0], aB0);  aB0 = fma2(bhi, wp[j][0][1], aB0);
            aB1 = fma2(blo, wp[j][1][0], aB1);  aB1 = fma2(bhi, wp[j][1][1], aB1);
            aB2 = fma2(blo, wp[j][2][0], aB2);  aB2 = fma2(bhi, wp[j][2][1], aB2);
        }
        float t0, t1;
        unpack2(aA0, t0, t1); float hA0 = t0 + t1;
        unpack2(aA1, t0, t1); float hA1 = t0 + t1;
        unpack2(aA2, t0, t1); float hA2 = t0 + t1;
        unpack2(aB0, t0, t1); float hB0 = t0 + t1;
        unpack2(aB1, t0, t1); float hB1 = t0 + t1;
        unpack2(aB2, t0, t1); float hB2 = t0 + t1;
        ull pA = pack2(hA0, hA1);
        ull pB = pack2(hB0, hB1);
#pragma unroll
        for (int off = 8; off; off >>= 1) {
            ull qA = __shfl_xor_sync(0xffffffffu, pA, off);
            ull qB = __shfl_xor_sync(0xffffffffu, pB, off);
            float rA = __shfl_xor_sync(0xffffffffu, hA2, off);
            float rB = __shfl_xor_sync(0xffffffffu, hB2, off);
            pA = add2(pA, qA);
            pB = add2(pB, qB);
            hA2 += rA;
            hB2 += rB;
        }
        if (sub == 0) {
            float x0, x1;
            unpack2(pA, x0, x1);
            g_hs[nA] = make_float4(x0, x1, hA2, 0.0f);
            unpack2(pB, x0, x1);
            g_hs[nB] = make_float4(x0, x1, hB2, 0.0f);
        }
    }
}

// K3: node pass — dinv = rsqrt(deg+1); hs = h*dinv; agg1 = hs (self loop)
__global__ void k_node(int N) {
    cudaGridDependencySynchronize();
    int n = blockIdx.x * blockDim.x + threadIdx.x;
    if (n >= N) return;
    float dv = rsqrtf(g_deg[n] + 1.0f);
    g_dinv[n] = dv;
    float4 h = g_hs[n];
    float4 hs = make_float4(h.x * dv, h.y * dv, h.z * dv, 0.0f);
    g_hs[n] = hs;
    g_agg1[n] = hs;
}

// K4: layer-1 scatter: agg1[d] += hs[s]   (4 edges/thread)
__global__ __launch_bounds__(256)
void k_edge1(const int* __restrict__ ei, int E) {
    cudaGridDependencySynchronize();
    int stride = gridDim.x * blockDim.x;
    int i = blockIdx.x * blockDim.x + threadIdx.x;
    int E4 = E >> 2;
    const int4* s4 = (const int4*)ei;
    const int4* d4 = (const int4*)(ei + E);
    for (int e = i; e < E4; e += stride) {
        int4 s = s4[e];
        int4 d = d4[e];
        float4 h0 = g_hs[s.x];
        float4 h1 = g_hs[s.y];
        float4 h2 = g_hs[s.z];
        float4 h3 = g_hs[s.w];
        red4(&g_agg1[d.x], h0.x, h0.y, h0.z);
        red4(&g_agg1[d.y], h1.x, h1.y, h1.z);
        red4(&g_agg1[d.z], h2.x, h2.y, h2.z);
        red4(&g_agg1[d.w], h3.x, h3.y, h3.z);
    }
    for (int e = (E4 << 2) + i; e < E; e += stride) {
        int s = ei[e], d = ei[E + e];
        float4 h = g_hs[s];
        red4(&g_agg1[d], h.x, h.y, h.z);
    }
}

// K5: finalize layer1: a = agg1*dinv (+b1, relu) -> h2 -> t = h2*dinv.
//     Seed window accumulator g_u with self-loop term t[n].
__global__ void k_final1(const float* __restrict__ b1,
                         const float* __restrict__ W2, int N) {
    cudaGridDependencySynchronize();
    int n = blockIdx.x * blockDim.x + threadIdx.x;
    if (n >= N) return;
    float dv = g_dinv[n];
    float4 a = g_agg1[n];
    float o0 = fmaxf(a.x * dv + b1[0], 0.0f);
    float o1 = fmaxf(a.y * dv + b1[1], 0.0f);
    float o2 = fmaxf(a.z * dv + b1[2], 0.0f);
    float h2 = o0 * W2[0] + o1 * W2[1] + o2 * W2[2];
    float t = h2 * dv;
    g_t[n] = t;
    int r = n & (ILEN - 1);
    if (r < PLEN)
        g_u[(n >> 12) * PLEN + r] = t;
}

// K6: layer-2 scatter, filtered, unnormalized: u[d] += t[s].
// src int4 loaded only if at least one of its 4 edges survives the filter.
__global__ __launch_bounds__(256)
void k_edge2(const int* __restrict__ ei, int E) {
    cudaGridDependencySynchronize();
    int stride = gridDim.x * blockDim.x;
    int i = blockIdx.x * blockDim.x + threadIdx.x;
    int E4 = E >> 2;
    const int4* s4 = (const int4*)ei;
    const int4* d4 = (const int4*)(ei + E);
    for (int e = i; e < E4; e += stride) {
        int4 d = d4[e];
        int r0 = d.x & (ILEN - 1);
        int r1 = d.y & (ILEN - 1);
        int r2 = d.z & (ILEN - 1);
        int r3 = d.w & (ILEN - 1);
        if ((r0 < PLEN) | (r1 < PLEN) | (r2 < PLEN) | (r3 < PLEN)) {
            int4 s = s4[e];
            if (r0 < PLEN) atomicAdd(&g_u[(d.x >> 12) * PLEN + r0], g_t[s.x]);
            if (r1 < PLEN) atomicAdd(&g_u[(d.y >> 12) * PLEN + r1], g_t[s.y]);
            if (r2 < PLEN) atomicAdd(&g_u[(d.z >> 12) * PLEN + r2], g_t[s.z]);
            if (r3 < PLEN) atomicAdd(&g_u[(d.w >> 12) * PLEN + r3], g_t[s.w]);
        }
    }
    for (int e = (E4 << 2) + i; e < E; e += stride) {
        int d = ei[E + e];
        int r = d & (ILEN - 1);
        if (r < PLEN)
            atomicAdd(&g_u[(d >> 12) * PLEN + r], g_t[ei[e]]);
    }
}

// K7: final output: out = u * dinv[node] + b2.  Also re-zeroes g_deg to
// restore the entry invariant for the next execution/graph replay.
__global__ void k_out(const float* __restrict__ b2, float* __restrict__ out,
                      int N) {
    cudaGridDependencySynchronize();
    int i = blockIdx.x * blockDim.x + threadIdx.x;
    if (i < N) g_deg[i] = 0.0f;
    if (i >= WTOT) return;
    int n = (i >> 10) * ILEN + (i & (PLEN - 1));
    out[i] = g_u[i] * g_dinv[n] + b2[0];
}

// ---------------------------------------------------------------------------
static void launch_pdl(const void* fn, dim3 grid, dim3 block, void** args) {
    cudaLaunchConfig_t cfg = {};
    cfg.gridDim  = grid;
    cfg.blockDim = block;
    cfg.stream   = 0;
    cudaLaunchAttribute attr[1];
    attr[0].id = cudaLaunchAttributeProgrammaticStreamSerialization;
    attr[0].val.programmaticStreamSerializationAllowed = 1;
    cfg.attrs = attr;
    cfg.numAttrs = 1;
    cudaLaunchKernelExC(&cfg, fn, args);
}

extern "C" void kernel_launch(void* const* d_in, const int* in_sizes, int n_in,
                              void* d_out, int out_size) {
    const float* X   = (const float*)d_in[0];   // [N,256]
    const float* W1  = (const float*)d_in[1];   // [256,3]
    const float* b1  = (const float*)d_in[2];   // [3]
    const float* W2  = (const float*)d_in[3];   // [3,1]
    const float* b2  = (const float*)d_in[4];   // [1]
    const int*   ei  = (const int*)d_in[5];     // [2,E]
    float*       out = (float*)d_out;

    int N = in_sizes[0] / 256;
    int E = in_sizes[5] / 2;

    const int T = 256;
    int nb_node = (N + T - 1) / T;

    const int* dstp = ei + E;
    {   // k_fused (g_deg already zero: .bss init / re-zeroed by k_out)
        k_fused<<<DEG_B + 768, T>>>((const longlong2*)X, W1, dstp, N, E);
    }
    {   // k_node
        void* args[] = { &N };
        launch_pdl((const void*)k_node, dim3(nb_node), dim3(T), args);
    }
    {   // k_edge1
        void* args[] = { (void*)&ei, &E };
        launch_pdl((const void*)k_edge1, dim3(4096), dim3(T), args);
    }
    {   // k_final1
        void* args[] = { (void*)&b1, (void*)&W2, &N };
        launch_pdl((const void*)k_final1, dim3(nb_node), dim3(T), args);
    }
    {   // k_edge2
        void* args[] = { (void*)&ei, &E };
        launch_pdl((const void*)k_edge2, dim3(4096), dim3(T), args);
    }
    {   // k_out (covers N threads: zeroes g_deg, writes WTOT outputs)
        void* args[] = { (void*)&b2, (void*)&out, &N };
        launch_pdl((const void*)k_out, dim3(nb_node), dim3(T), args);
    }
}